// round 17
// baseline (speedup 1.0000x reference)
#include <cuda_runtime.h>
#include <cstdint>

// MessagePassing: out[src[e], k] += edge_attrs_flat[k*E + e]
// edge_attrs: float32 [E*F] (values consumed as (F,E): contiguous in e per feature)
// attr_idx:   [2*E] ints (row 0 = src); int32 or int64, sniffed once in zero kernel
// out:        float32 [N*F]
//
// Layout: a 4-lane group owns 4 consecutive edges; lane kgq owns feature
// quarter kg. float4 loads along e are dense 128B lines; each RED.v4 covers
// one node's contiguous 64B row with 4 lanes (8 node lines per warp instr).
// 3 chunks per thread, software-pipelined: ldA ldB redA ldC redB redC.

static constexpr int F = 16;
static constexpr int TPB = 256;

__device__ int g_idx_is64;

__global__ void zero_out_kernel(float4* __restrict__ out4, int n4,
                                const int* __restrict__ idx32, long long E) {
    // Block 0, lanes 0-63: idx dtype sniff. Under little-endian int64 the
    // int32 word at position 2e+1 is a high word -> 0. Random int32 indices
    // in [0,100000) are nonzero w.p. 1-1e-5; 64 all-zero samples => int64.
    if (blockIdx.x == 0) {
        __shared__ int s_not64;
        if (threadIdx.x == 0) s_not64 = 0;
        __syncthreads();
        if (threadIdx.x < 64) {
            long long e = ((long long)threadIdx.x * (E / 64)) % E;
            if (__ldcs(idx32 + (2 * e + 1)) != 0) atomicOr(&s_not64, 1);
        }
        __syncthreads();
        if (threadIdx.x == 0) g_idx_is64 = !s_not64;
    }
    int i = blockIdx.x * blockDim.x + threadIdx.x;
    if (i < n4) out4[i] = make_float4(0.f, 0.f, 0.f, 0.f);
}

struct Chunk {
    int src[4];
    float4 v0, v1, v2, v3;
};

__device__ __forceinline__ void load_chunk(const float* __restrict__ attrs,
                                           const void* __restrict__ src_idx,
                                           bool is64, long long E, long long group,
                                           int kg, Chunk& c) {
    size_t e0 = (size_t)group * 4;
    if (is64) {
        const longlong2* p = (const longlong2*)src_idx + 2 * group;
        longlong2 a = __ldcs(p);
        longlong2 b = __ldcs(p + 1);
        c.src[0] = (int)a.x; c.src[1] = (int)a.y;
        c.src[2] = (int)b.x; c.src[3] = (int)b.y;
    } else {
        int4 a = __ldcs((const int4*)src_idx + group);
        c.src[0] = a.x; c.src[1] = a.y; c.src[2] = a.z; c.src[3] = a.w;
    }
    c.v0 = __ldcs((const float4*)(attrs + (size_t)(kg + 0) * (size_t)E + e0));
    c.v1 = __ldcs((const float4*)(attrs + (size_t)(kg + 1) * (size_t)E + e0));
    c.v2 = __ldcs((const float4*)(attrs + (size_t)(kg + 2) * (size_t)E + e0));
    c.v3 = __ldcs((const float4*)(attrs + (size_t)(kg + 3) * (size_t)E + e0));
}

__device__ __forceinline__ void red_chunk(float* __restrict__ out, int kg,
                                          const Chunk& c) {
    const float* c0 = (const float*)&c.v0;
    const float* c1 = (const float*)&c.v1;
    const float* c2 = (const float*)&c.v2;
    const float* c3 = (const float*)&c.v3;
#pragma unroll
    for (int j = 0; j < 4; j++) {
        float* dst = out + (size_t)c.src[j] * F + kg;
        asm volatile(
            "red.global.add.v4.f32 [%0], {%1, %2, %3, %4};"
            :: "l"(dst), "f"(c0[j]), "f"(c1[j]), "f"(c2[j]), "f"(c3[j])
            : "memory");
    }
}

__global__ void __launch_bounds__(TPB, 3)
scatter_rt3_kernel(const float* __restrict__ attrs,
                   const void* __restrict__ src_idx,
                   float* __restrict__ out,
                   long long E, long long G3) {
    bool is64 = (g_idx_is64 != 0);

    long long gtid = (long long)blockIdx.x * TPB + threadIdx.x;
    long long ga = gtid >> 2;           // first 4-edge group
    int kg = ((int)gtid & 3) * 4;       // this lane's feature quarter
    if (ga >= G3) return;
    long long gb = ga + G3;
    long long gc = gb + G3;

    // Software pipeline: ldA ldB | redA ldC | redB redC.
    Chunk A, B, C;
    load_chunk(attrs, src_idx, is64, E, ga, kg, A);
    load_chunk(attrs, src_idx, is64, E, gb, kg, B);
    red_chunk(out, kg, A);
    load_chunk(attrs, src_idx, is64, E, gc, kg, C);
    red_chunk(out, kg, B);
    red_chunk(out, kg, C);
}

// Scalar tail for leftover edges (E % 12 != 0): at most 11 edges, one block.
__global__ void scatter_tail_kernel(const float* __restrict__ attrs,
                                    const void* __restrict__ src_idx,
                                    float* __restrict__ out,
                                    long long E, long long e_begin) {
    bool is64 = (g_idx_is64 != 0);
    long long e = e_begin + (long long)blockIdx.x * blockDim.x + threadIdx.x;
    if (e >= E) return;
    int src = is64 ? (int)((const long long*)src_idx)[e]
                   : ((const int*)src_idx)[e];
    float v[F];
#pragma unroll
    for (int k = 0; k < F; k++) v[k] = attrs[(size_t)k * (size_t)E + e];
    float* dst = out + (size_t)src * F;
#pragma unroll
    for (int kg = 0; kg < F; kg += 4) {
        asm volatile(
            "red.global.add.v4.f32 [%0], {%1, %2, %3, %4};"
            :: "l"(dst + kg), "f"(v[kg]), "f"(v[kg + 1]), "f"(v[kg + 2]), "f"(v[kg + 3])
            : "memory");
    }
}

extern "C" void kernel_launch(void* const* d_in, const int* in_sizes, int n_in,
                              void* d_out, int out_size) {
    const float* attrs = (const float*)d_in[0];
    const void* attr_idx = d_in[1];        // (2, E), row 0 = src
    float* out = (float*)d_out;

    long long E = in_sizes[0] / F;

    int n4 = out_size / 4;
    zero_out_kernel<<<(n4 + 255) / 256, 256>>>((float4*)out, n4,
                                               (const int*)attr_idx, E);

    long long G = E / 4;                   // full 4-edge groups
    long long G3 = G / 3;                  // chunk triples
    if (G3 > 0) {
        long long n_threads = G3 * 4;
        int blocks = (int)((n_threads + TPB - 1) / TPB);
        scatter_rt3_kernel<<<blocks, TPB>>>(attrs, attr_idx, out, E, G3);
    }

    long long rem_begin = G3 * 12;         // edges covered by chunk triples
    long long rem = E - rem_begin;
    if (rem > 0) {
        int blocks = (int)((rem + 255) / 256);
        scatter_tail_kernel<<<blocks, 256>>>(attrs, attr_idx, out, E, rem_begin);
    }
}